// round 6
// baseline (speedup 1.0000x reference)
#include <cuda_runtime.h>
#include <cuda_bf16.h>

#define NB 8
#define NPTS 16384
#define NQ 1024
#define NC 64
#define NS 32
#define R2 0.04f
#define WPB 4   // warps per block (main kernel)

// 2 MB scratch: xyz packed as float4 for single-LDG.128 scan loads.
__device__ float4 g_xyz4[(size_t)NB * NPTS];
// 33.5 MB scratch: features transposed to (B, N, C); fits in L2 (126 MB).
__device__ float g_feats_t[(size_t)NB * NPTS * NC];

#define TBLOCKS (NB * (NPTS / 32))      // 4096 transpose tiles
#define PBLOCKS ((NB * NPTS) / 256)     // 512 pack blocks

// ---- fused pre-pass: feats transpose + xyz pack (job by blockIdx.x) ----
__global__ __launch_bounds__(256) void prepass_kernel(
    const float* __restrict__ xyz, const float* __restrict__ feats)
{
    if (blockIdx.x < TBLOCKS) {
        // transpose (B,C,N) -> (B,N,C), one 32-point x 64-channel tile
        __shared__ float tile[32][65];
        const int b  = blockIdx.x >> 9;          // / (NPTS/32)
        const int n0 = (blockIdx.x & 511) * 32;
        const int t  = threadIdx.x;
        const int tx = t & 31;                   // n within tile
        const int ty = t >> 5;                   // c base (0..7)

        const float* src = feats + (size_t)b * NC * NPTS + n0;
        #pragma unroll
        for (int k = 0; k < 8; ++k) {
            const int c = ty * 8 + k;
            tile[tx][c] = src[(size_t)c * NPTS + tx];
        }
        __syncthreads();

        float* dst = g_feats_t + ((size_t)b * NPTS + n0) * NC;
        #pragma unroll
        for (int k = 0; k < 8; ++k) {
            const int idx = k * 256 + t;
            const int n = idx >> 6;
            const int c = idx & 63;
            dst[(size_t)n * NC + c] = tile[n][c];
        }
    } else {
        // pack (B,N,3) f32 -> (B,N) float4
        __shared__ float sbuf[8][96];
        const int bid  = blockIdx.x - TBLOCKS;
        const int warp = threadIdx.x >> 5, lane = threadIdx.x & 31;
        const size_t base = (size_t)bid * 256 + warp * 32;
        const float* src = xyz + base * 3;
        float* s = sbuf[warp];
        s[lane]      = src[lane];
        s[lane + 32] = src[lane + 32];
        s[lane + 64] = src[lane + 64];
        __syncwarp();
        g_xyz4[base + lane] = make_float4(s[lane * 3], s[lane * 3 + 1], s[lane * 3 + 2], 0.f);
    }
}

// ---- main: software-pipelined ball-query scan + float4 grouped gather ----
__global__ __launch_bounds__(WPB * 32) void qag_kernel(
    const float* __restrict__ new_xyz,  // (B, S, 3)
    float* __restrict__ out)            // (B, 3+C, S, NS)
{
    const int lane = threadIdx.x & 31;
    const int wid  = threadIdx.x >> 5;
    const int q = blockIdx.x * WPB + wid;      // global query id in [0, B*S)
    const int b = q >> 10;                     // / NQ
    const int s = q & (NQ - 1);

    // 160 slots: 31 existing + up to 128 appended in the crossing chunk;
    // hot loop skips the pos<NS bounds check entirely.
    __shared__ int idx_buf_all[WPB][NS + 128];
    int* idx_buf = idx_buf_all[wid];

    const float qx = new_xyz[q * 3 + 0];
    const float qy = new_xyz[q * 3 + 1];
    const float qz = new_xyz[q * 3 + 2];

    const float4* __restrict__ xb4 = g_xyz4 + (size_t)b * NPTS;
    const unsigned lt = (1u << lane) - 1u;

    // ---- ball query: 128-pt chunks, prefetch next chunk before processing ----
    int cnt = 0;
    float4 p[4];
    #pragma unroll
    for (int u = 0; u < 4; ++u) p[u] = xb4[u * 32 + lane];

    for (int j0 = 0; j0 < NPTS; j0 += 128) {
        // speculative prefetch of next chunk (wrapped -> always in bounds)
        const int jn = (j0 + 128) & (NPTS - 1);
        float4 np[4];
        #pragma unroll
        for (int u = 0; u < 4; ++u) np[u] = xb4[jn + u * 32 + lane];

        // process current chunk (exact same d2 arithmetic as passing rounds)
        bool w[4];
        #pragma unroll
        for (int u = 0; u < 4; ++u) {
            const float dx = p[u].x - qx;
            const float dy = p[u].y - qy;
            const float dz = p[u].z - qz;
            w[u] = dx * dx + dy * dy + dz * dz < R2;
        }
        unsigned m[4];
        #pragma unroll
        for (int u = 0; u < 4; ++u) m[u] = __ballot_sync(0xFFFFFFFFu, w[u]);

        int base = cnt;
        #pragma unroll
        for (int u = 0; u < 4; ++u) {
            if (w[u]) idx_buf[base + __popc(m[u] & lt)] = j0 + u * 32 + lane;
            base += __popc(m[u]);
        }
        cnt = base;
        if (cnt >= NS) break;   // uniform across warp

        #pragma unroll
        for (int u = 0; u < 4; ++u) p[u] = np[u];
    }
    __syncwarp();
    const int eff = cnt < NS ? cnt : NS;
    int first = 0;
    if (eff > 0) first = idx_buf[0];
    __syncwarp();
    if (lane >= eff) idx_buf[lane] = first;   // pad with first valid (0 if none)
    __syncwarp();
    const int my = idx_buf[lane];             // lane k owns sample k

    // ---- grouped xyz (channels 0..2), coalesced writes ----
    const float4 P = xb4[my];
    const size_t CH = (size_t)NQ * NS;                         // channel stride
    float* ob = out + ((size_t)b * (3 + NC) * NQ + s) * NS + lane;
    ob[0 * CH] = P.x - qx;
    ob[1 * CH] = P.y - qy;
    ob[2 * CH] = P.z - qz;

    // ---- grouped features: float4 row gather, lane = sample, MLP=8 ----
    const float4* __restrict__ fb =
        (const float4*)(g_feats_t + (size_t)b * NPTS * NC) + (size_t)my * (NC / 4);
    float* of = ob + 3 * CH;
    #pragma unroll
    for (int half = 0; half < 2; ++half) {
        float4 v[8];
        #pragma unroll
        for (int g = 0; g < 8; ++g) v[g] = __ldg(fb + half * 8 + g);
        #pragma unroll
        for (int g = 0; g < 8; ++g) {
            const int c = (half * 8 + g) * 4;
            of[(size_t)(c + 0) * CH] = v[g].x;
            of[(size_t)(c + 1) * CH] = v[g].y;
            of[(size_t)(c + 2) * CH] = v[g].z;
            of[(size_t)(c + 3) * CH] = v[g].w;
        }
    }
}

extern "C" void kernel_launch(void* const* d_in, const int* in_sizes, int n_in,
                              void* d_out, int out_size) {
    const float* xyz     = (const float*)d_in[0];
    const float* new_xyz = (const float*)d_in[1];
    const float* feats   = (const float*)d_in[2];
    float* out = (float*)d_out;

    prepass_kernel<<<TBLOCKS + PBLOCKS, 256>>>(xyz, feats);

    const int nq = NB * NQ;                 // 8192 queries, one warp each
    qag_kernel<<<nq / WPB, WPB * 32>>>(new_xyz, out);
}

// round 7
// speedup vs baseline: 1.5686x; 1.5686x over previous
#include <cuda_runtime.h>
#include <cuda_bf16.h>

#define NB 8
#define NPTS 16384
#define NQ 1024
#define NC 64
#define NS 32
#define R2 0.04f

// 2 MB scratch: xyz packed as float4 for single-LDG.128 scan loads.
__device__ float4 g_xyz4[(size_t)NB * NPTS];
// 33.5 MB scratch: features transposed to (B, N, C); fits in L2 (126 MB).
__device__ float g_feats_t[(size_t)NB * NPTS * NC];

#define TBLOCKS (NB * (NPTS / 32))      // 4096 transpose tiles
#define PBLOCKS ((NB * NPTS) / 256)     // 512 pack blocks

// ---- fused pre-pass: feats transpose + xyz pack (job by blockIdx.x) ----
__global__ __launch_bounds__(256) void prepass_kernel(
    const float* __restrict__ xyz, const float* __restrict__ feats)
{
    if (blockIdx.x < TBLOCKS) {
        __shared__ float tile[32][65];
        const int b  = blockIdx.x >> 9;          // / (NPTS/32)
        const int n0 = (blockIdx.x & 511) * 32;
        const int t  = threadIdx.x;
        const int tx = t & 31;
        const int ty = t >> 5;

        const float* src = feats + (size_t)b * NC * NPTS + n0;
        #pragma unroll
        for (int k = 0; k < 8; ++k) {
            const int c = ty * 8 + k;
            tile[tx][c] = src[(size_t)c * NPTS + tx];
        }
        __syncthreads();

        float* dst = g_feats_t + ((size_t)b * NPTS + n0) * NC;
        #pragma unroll
        for (int k = 0; k < 8; ++k) {
            const int idx = k * 256 + t;
            const int n = idx >> 6;
            const int c = idx & 63;
            dst[(size_t)n * NC + c] = tile[n][c];
        }
    } else {
        __shared__ float sbuf[8][96];
        const int bid  = blockIdx.x - TBLOCKS;
        const int warp = threadIdx.x >> 5, lane = threadIdx.x & 31;
        const size_t base = (size_t)bid * 256 + warp * 32;
        const float* src = xyz + base * 3;
        float* s = sbuf[warp];
        s[lane]      = src[lane];
        s[lane + 32] = src[lane + 32];
        s[lane + 64] = src[lane + 64];
        __syncwarp();
        g_xyz4[base + lane] = make_float4(s[lane * 3], s[lane * 3 + 1], s[lane * 3 + 2], 0.f);
    }
}

// ---- main: one block (4 warps) per query; 1024 points per round ----
__global__ __launch_bounds__(128) void qag_kernel(
    const float* __restrict__ new_xyz,  // (B, S, 3)
    float* __restrict__ out)            // (B, 3+C, S, NS)
{
    const int lane = threadIdx.x & 31;
    const int w    = threadIdx.x >> 5;         // warp id 0..3
    const int q = blockIdx.x;                  // one query per block
    const int b = q >> 10;                     // / NQ
    const int s = q & (NQ - 1);

    // 31 carried + up to 1024 appended in the crossing round: unchecked stores.
    __shared__ int idx_buf[NS + 1024];
    __shared__ int wtot[4];

    const float qx = new_xyz[q * 3 + 0];
    const float qy = new_xyz[q * 3 + 1];
    const float qz = new_xyz[q * 3 + 2];

    const float4* __restrict__ xb4 = g_xyz4 + (size_t)b * NPTS;
    const unsigned lt = (1u << lane) - 1u;

    // ---- ball query: 1024-pt rounds, warp w owns sub-chunk [w*256, w*256+256) ----
    int cnt = 0;
    for (int j0 = 0; j0 < NPTS; j0 += 1024) {
        const int jw = j0 + w * 256;
        float4 p[8];
        #pragma unroll
        for (int u = 0; u < 8; ++u) p[u] = xb4[jw + u * 32 + lane];

        bool wi[8];
        #pragma unroll
        for (int u = 0; u < 8; ++u) {
            const float dx = p[u].x - qx;
            const float dy = p[u].y - qy;
            const float dz = p[u].z - qz;
            wi[u] = dx * dx + dy * dy + dz * dz < R2;
        }
        unsigned m[8];
        #pragma unroll
        for (int u = 0; u < 8; ++u) m[u] = __ballot_sync(0xFFFFFFFFu, wi[u]);

        int tot = 0;
        #pragma unroll
        for (int u = 0; u < 8; ++u) tot += __popc(m[u]);
        if (lane == 0) wtot[w] = tot;
        __syncthreads();

        // warp's write base = carried count + counts of lower warps this round
        int base = cnt;
        #pragma unroll
        for (int ww = 0; ww < 4; ++ww) {
            const int t = wtot[ww];
            if (ww < w) base += t;
            cnt += t;
        }
        #pragma unroll
        for (int u = 0; u < 8; ++u) {
            if (wi[u]) idx_buf[base + __popc(m[u] & lt)] = jw + u * 32 + lane;
            base += __popc(m[u]);
        }
        __syncthreads();   // idx_buf visible; wtot safe for next round
        if (cnt >= NS) break;   // uniform across block
    }

    const int eff = cnt < NS ? cnt : NS;
    const int first = (eff > 0) ? idx_buf[0] : 0;
    if (w == 0 && lane >= eff) idx_buf[lane] = first;  // pad with first valid
    __syncthreads();
    const int my = idx_buf[lane];                      // lane k owns sample k

    const size_t CH = (size_t)NQ * NS;                 // channel stride
    float* ob = out + ((size_t)b * (3 + NC) * NQ + s) * NS + lane;

    // ---- grouped xyz (warp 0 only), coalesced writes ----
    if (w == 0) {
        const float4 P = xb4[my];
        ob[0 * CH] = P.x - qx;
        ob[1 * CH] = P.y - qy;
        ob[2 * CH] = P.z - qz;
    }

    // ---- grouped features: warp w handles float4-groups w*4..w*4+3 ----
    const float4* __restrict__ fb =
        (const float4*)(g_feats_t + (size_t)b * NPTS * NC) + (size_t)my * (NC / 4);
    float* of = ob + 3 * CH;
    float4 v[4];
    #pragma unroll
    for (int g = 0; g < 4; ++g) v[g] = __ldg(fb + w * 4 + g);
    #pragma unroll
    for (int g = 0; g < 4; ++g) {
        const int c = (w * 4 + g) * 4;
        of[(size_t)(c + 0) * CH] = v[g].x;
        of[(size_t)(c + 1) * CH] = v[g].y;
        of[(size_t)(c + 2) * CH] = v[g].z;
        of[(size_t)(c + 3) * CH] = v[g].w;
    }
}

extern "C" void kernel_launch(void* const* d_in, const int* in_sizes, int n_in,
                              void* d_out, int out_size) {
    const float* xyz     = (const float*)d_in[0];
    const float* new_xyz = (const float*)d_in[1];
    const float* feats   = (const float*)d_in[2];
    float* out = (float*)d_out;

    prepass_kernel<<<TBLOCKS + PBLOCKS, 256>>>(xyz, feats);

    qag_kernel<<<NB * NQ, 128>>>(new_xyz, out);   // one block per query
}

// round 8
// speedup vs baseline: 1.7392x; 1.1087x over previous
#include <cuda_runtime.h>
#include <cuda_bf16.h>

#define NB 8
#define NPTS 16384
#define NQ 1024
#define NC 64
#define NS 32
#define R2 0.04f

// 2 MB scratch: xyz packed as float4 for single-LDG.128 scan loads.
__device__ float4 g_xyz4[(size_t)NB * NPTS];
// 33.5 MB scratch: features transposed to (B, N, C); fits in L2 (126 MB).
__device__ float g_feats_t[(size_t)NB * NPTS * NC];

#define TBLOCKS (NB * (NPTS / 32))      // 4096 transpose tiles
#define PBLOCKS ((NB * NPTS) / 256)     // 512 pack blocks

// ---- fused pre-pass: feats transpose + xyz pack (job by blockIdx.x) ----
__global__ __launch_bounds__(256) void prepass_kernel(
    const float* __restrict__ xyz, const float* __restrict__ feats)
{
    if (blockIdx.x < TBLOCKS) {
        __shared__ float tile[32][65];
        const int b  = blockIdx.x >> 9;          // / (NPTS/32)
        const int n0 = (blockIdx.x & 511) * 32;
        const int t  = threadIdx.x;
        const int tx = t & 31;
        const int ty = t >> 5;

        const float* src = feats + (size_t)b * NC * NPTS + n0;
        #pragma unroll
        for (int k = 0; k < 8; ++k) {
            const int c = ty * 8 + k;
            tile[tx][c] = src[(size_t)c * NPTS + tx];
        }
        __syncthreads();

        float* dst = g_feats_t + ((size_t)b * NPTS + n0) * NC;
        #pragma unroll
        for (int k = 0; k < 8; ++k) {
            const int idx = k * 256 + t;
            const int n = idx >> 6;
            const int c = idx & 63;
            dst[(size_t)n * NC + c] = tile[n][c];
        }
    } else {
        __shared__ float sbuf[8][96];
        const int bid  = blockIdx.x - TBLOCKS;
        const int warp = threadIdx.x >> 5, lane = threadIdx.x & 31;
        const size_t base = (size_t)bid * 256 + warp * 32;
        const float* src = xyz + base * 3;
        float* s = sbuf[warp];
        s[lane]      = src[lane];
        s[lane + 32] = src[lane + 32];
        s[lane + 64] = src[lane + 64];
        __syncwarp();
        g_xyz4[base + lane] = make_float4(s[lane * 3], s[lane * 3 + 1], s[lane * 3 + 2], 0.f);
    }
}

// ---- main: one block (4 warps) per query; 1024 pts/round; smem-bounced gather ----
__global__ __launch_bounds__(128) void qag_kernel(
    const float* __restrict__ new_xyz,  // (B, S, 3)
    float* __restrict__ out)            // (B, 3+C, S, NS)
{
    const int lane = threadIdx.x & 31;
    const int w    = threadIdx.x >> 5;         // warp id 0..3
    const int q = blockIdx.x;                  // one query per block
    const int b = q >> 10;                     // / NQ
    const int s = q & (NQ - 1);

    // 31 carried + up to 1024 appended in the crossing round: unchecked stores.
    __shared__ int   idx_buf[NS + 1024];
    __shared__ int   wtot[2][4];               // double-buffered per-warp counts
    __shared__ float fsm[NC * 33];             // [channel][sample], stride 33

    const float qx = new_xyz[q * 3 + 0];
    const float qy = new_xyz[q * 3 + 1];
    const float qz = new_xyz[q * 3 + 2];

    const float4* __restrict__ xb4 = g_xyz4 + (size_t)b * NPTS;
    const unsigned lt = (1u << lane) - 1u;

    // ---- ball query: 1024-pt rounds, warp w owns sub-chunk [w*256, +256) ----
    int cnt = 0;
    int pb = 0;
    for (int j0 = 0; j0 < NPTS; j0 += 1024) {
        const int jw = j0 + w * 256;
        float4 p[8];
        #pragma unroll
        for (int u = 0; u < 8; ++u) p[u] = xb4[jw + u * 32 + lane];

        bool wi[8];
        #pragma unroll
        for (int u = 0; u < 8; ++u) {
            const float dx = p[u].x - qx;
            const float dy = p[u].y - qy;
            const float dz = p[u].z - qz;
            wi[u] = dx * dx + dy * dy + dz * dz < R2;
        }
        unsigned m[8];
        #pragma unroll
        for (int u = 0; u < 8; ++u) m[u] = __ballot_sync(0xFFFFFFFFu, wi[u]);

        int tot = 0;
        #pragma unroll
        for (int u = 0; u < 8; ++u) tot += __popc(m[u]);
        if (lane == 0) wtot[pb][w] = tot;
        __syncthreads();

        // warp's write base = carried count + counts of lower warps this round
        int base = cnt;
        #pragma unroll
        for (int ww = 0; ww < 4; ++ww) {
            const int t = wtot[pb][ww];
            if (ww < w) base += t;
            cnt += t;
        }
        #pragma unroll
        for (int u = 0; u < 8; ++u) {
            if (wi[u]) idx_buf[base + __popc(m[u] & lt)] = jw + u * 32 + lane;
            base += __popc(m[u]);
        }
        pb ^= 1;                // next round uses the other wtot buffer
        if (cnt >= NS) break;   // uniform across block
    }
    __syncthreads();            // idx_buf (final round) visible to all warps

    const int eff = cnt < NS ? cnt : NS;
    const int first = (eff > 0) ? idx_buf[0] : 0;
    if (w == 0 && lane >= eff) idx_buf[lane] = first;  // pad with first valid
    __syncthreads();

    const size_t CH = (size_t)NQ * NS;                 // channel stride
    float* ob = out + ((size_t)b * (3 + NC) * NQ + s) * NS + lane;

    // ---- grouped xyz (warp 0 only), coalesced writes ----
    if (w == 0) {
        const float4 P = xb4[idx_buf[lane]];
        ob[0 * CH] = P.x - qx;
        ob[1 * CH] = P.y - qy;
        ob[2 * CH] = P.z - qz;
    }

    // ---- grouped features: half-warp per sample row (2 rows / instruction) ----
    // warp w loads samples 8w..8w+7; lane g=lane&15 owns float4 group g.
    {
        const float4* __restrict__ fbase = (const float4*)(g_feats_t + (size_t)b * NPTS * NC);
        const int g    = lane & 15;
        const int half = lane >> 4;
        #pragma unroll
        for (int i = 0; i < 4; ++i) {
            const int msamp = 8 * w + 2 * i + half;
            const int im = idx_buf[msamp];
            const float4 v = __ldg(fbase + (size_t)im * (NC / 4) + g);
            fsm[(4 * g + 0) * 33 + msamp] = v.x;
            fsm[(4 * g + 1) * 33 + msamp] = v.y;
            fsm[(4 * g + 2) * 33 + msamp] = v.z;
            fsm[(4 * g + 3) * 33 + msamp] = v.w;
        }
    }
    __syncthreads();

    // ---- writeout: warp w covers channels 16w..16w+15, lane = sample ----
    float* of = ob + 3 * CH;
    #pragma unroll
    for (int c = 0; c < 16; ++c) {
        const int ch = 16 * w + c;
        of[(size_t)ch * CH] = fsm[ch * 33 + lane];
    }
}

extern "C" void kernel_launch(void* const* d_in, const int* in_sizes, int n_in,
                              void* d_out, int out_size) {
    const float* xyz     = (const float*)d_in[0];
    const float* new_xyz = (const float*)d_in[1];
    const float* feats   = (const float*)d_in[2];
    float* out = (float*)d_out;

    prepass_kernel<<<TBLOCKS + PBLOCKS, 256>>>(xyz, feats);

    qag_kernel<<<NB * NQ, 128>>>(new_xyz, out);   // one block per query
}

// round 9
// speedup vs baseline: 1.7887x; 1.0285x over previous
#include <cuda_runtime.h>
#include <cuda_bf16.h>

#define NB 8
#define NPTS 16384
#define NQ 1024
#define NC 64
#define NS 32
#define R2 0.04f

// 2 MB scratch: xyz packed as float4 for single-LDG.128 scan loads.
__device__ float4 g_xyz4[(size_t)NB * NPTS];
// 33.5 MB scratch: features transposed to (B, N, C); fits in L2 (126 MB).
__device__ float g_feats_t[(size_t)NB * NPTS * NC];

#define TBLOCKS (NB * (NPTS / 32))      // 4096 transpose tiles
#define PBLOCKS ((NB * NPTS) / 256)     // 512 pack blocks

// ---- fused pre-pass: feats transpose + xyz pack (job by blockIdx.x) ----
__global__ __launch_bounds__(256) void prepass_kernel(
    const float* __restrict__ xyz, const float* __restrict__ feats)
{
    if (blockIdx.x < TBLOCKS) {
        __shared__ float tile[32][65];
        const int b  = blockIdx.x >> 9;          // / (NPTS/32)
        const int n0 = (blockIdx.x & 511) * 32;
        const int t  = threadIdx.x;
        const int tx = t & 31;
        const int ty = t >> 5;

        const float* src = feats + (size_t)b * NC * NPTS + n0;
        #pragma unroll
        for (int k = 0; k < 8; ++k) {
            const int c = ty * 8 + k;
            tile[tx][c] = src[(size_t)c * NPTS + tx];
        }
        __syncthreads();

        float* dst = g_feats_t + ((size_t)b * NPTS + n0) * NC;
        #pragma unroll
        for (int k = 0; k < 8; ++k) {
            const int idx = k * 256 + t;
            const int n = idx >> 6;
            const int c = idx & 63;
            dst[(size_t)n * NC + c] = tile[n][c];
        }
    } else {
        __shared__ float sbuf[8][96];
        const int bid  = blockIdx.x - TBLOCKS;
        const int warp = threadIdx.x >> 5, lane = threadIdx.x & 31;
        const size_t base = (size_t)bid * 256 + warp * 32;
        const float* src = xyz + base * 3;
        float* s = sbuf[warp];
        s[lane]      = src[lane];
        s[lane + 32] = src[lane + 32];
        s[lane + 64] = src[lane + 64];
        __syncwarp();
        g_xyz4[base + lane] = make_float4(s[lane * 3], s[lane * 3 + 1], s[lane * 3 + 2], 0.f);
    }
}

#define FSTRIDE 68   // fsm row stride in floats: 4L-pattern banks, 16B aligned

// ---- main: one block (4 warps) per query; 1024 pts/round; vector smem gather ----
__global__ __launch_bounds__(128) void qag_kernel(
    const float* __restrict__ new_xyz,  // (B, S, 3)
    float* __restrict__ out)            // (B, 3+C, S, NS)
{
    const int lane = threadIdx.x & 31;
    const int w    = threadIdx.x >> 5;         // warp id 0..3
    const int q = blockIdx.x;                  // one query per block
    const int b = q >> 10;                     // / NQ
    const int s = q & (NQ - 1);

    // 31 carried + up to 1024 appended in the crossing round: unchecked stores.
    __shared__ int   idx_buf[NS + 1024];
    __shared__ int   wtot[2][4];               // double-buffered per-warp counts
    __shared__ float fsm[NS * FSTRIDE];        // [sample][channel], stride 68

    const float qx = new_xyz[q * 3 + 0];
    const float qy = new_xyz[q * 3 + 1];
    const float qz = new_xyz[q * 3 + 2];

    const float4* __restrict__ xb4 = g_xyz4 + (size_t)b * NPTS;
    const unsigned lt = (1u << lane) - 1u;

    // ---- ball query: 1024-pt rounds, warp w owns sub-chunk [w*256, +256) ----
    int cnt = 0;
    int pb = 0;
    for (int j0 = 0; j0 < NPTS; j0 += 1024) {
        const int jw = j0 + w * 256;
        float4 p[8];
        #pragma unroll
        for (int u = 0; u < 8; ++u) p[u] = xb4[jw + u * 32 + lane];

        bool wi[8];
        #pragma unroll
        for (int u = 0; u < 8; ++u) {
            const float dx = p[u].x - qx;
            const float dy = p[u].y - qy;
            const float dz = p[u].z - qz;
            wi[u] = dx * dx + dy * dy + dz * dz < R2;
        }
        unsigned m[8];
        #pragma unroll
        for (int u = 0; u < 8; ++u) m[u] = __ballot_sync(0xFFFFFFFFu, wi[u]);

        int tot = 0;
        #pragma unroll
        for (int u = 0; u < 8; ++u) tot += __popc(m[u]);
        if (lane == 0) wtot[pb][w] = tot;
        __syncthreads();

        // warp's write base = carried count + counts of lower warps this round
        int base = cnt;
        #pragma unroll
        for (int ww = 0; ww < 4; ++ww) {
            const int t = wtot[pb][ww];
            if (ww < w) base += t;
            cnt += t;
        }
        #pragma unroll
        for (int u = 0; u < 8; ++u) {
            if (wi[u]) idx_buf[base + __popc(m[u] & lt)] = jw + u * 32 + lane;
            base += __popc(m[u]);
        }
        pb ^= 1;                // next round uses the other wtot buffer
        if (cnt >= NS) break;   // uniform across block
    }
    __syncthreads();            // idx_buf (final round) visible to all warps

    const int eff = cnt < NS ? cnt : NS;
    const int first = (eff > 0) ? idx_buf[0] : 0;   // pad value, computed inline

    const size_t CH = (size_t)NQ * NS;              // channel stride
    float* ob = out + ((size_t)b * (3 + NC) * NQ + s) * NS + lane;

    // ---- grouped xyz (warp 0 only), coalesced writes ----
    if (w == 0) {
        const int im = (lane < eff) ? idx_buf[lane] : first;
        const float4 P = xb4[im];
        ob[0 * CH] = P.x - qx;
        ob[1 * CH] = P.y - qy;
        ob[2 * CH] = P.z - qz;
    }

    // ---- grouped features: half-warp per sample row -> fsm via STS.128 ----
    // warp w loads samples 8w..8w+7; lane g=lane&15 owns float4 group g.
    {
        const float4* __restrict__ fbase = (const float4*)(g_feats_t + (size_t)b * NPTS * NC);
        const int g    = lane & 15;
        const int half = lane >> 4;
        #pragma unroll
        for (int i = 0; i < 4; ++i) {
            const int msamp = 8 * w + 2 * i + half;
            const int im = (msamp < eff) ? idx_buf[msamp] : first;
            const float4 v = __ldg(fbase + (size_t)im * (NC / 4) + g);
            *(float4*)&fsm[msamp * FSTRIDE + 4 * g] = v;   // STS.128, conflict-free
        }
    }
    __syncthreads();

    // ---- writeout: warp w covers channels 16w..16w+15 via LDS.128, lane = sample ----
    float* of = ob + 3 * CH;
    #pragma unroll
    for (int c4 = 0; c4 < 4; ++c4) {
        const int ch0 = 16 * w + 4 * c4;
        const float4 fv = *(const float4*)&fsm[lane * FSTRIDE + ch0];  // conflict-free
        of[(size_t)(ch0 + 0) * CH] = fv.x;
        of[(size_t)(ch0 + 1) * CH] = fv.y;
        of[(size_t)(ch0 + 2) * CH] = fv.z;
        of[(size_t)(ch0 + 3) * CH] = fv.w;
    }
}

extern "C" void kernel_launch(void* const* d_in, const int* in_sizes, int n_in,
                              void* d_out, int out_size) {
    const float* xyz     = (const float*)d_in[0];
    const float* new_xyz = (const float*)d_in[1];
    const float* feats   = (const float*)d_in[2];
    float* out = (float*)d_out;

    prepass_kernel<<<TBLOCKS + PBLOCKS, 256>>>(xyz, feats);

    qag_kernel<<<NB * NQ, 128>>>(new_xyz, out);   // one block per query
}